// round 13
// baseline (speedup 1.0000x reference)
#include <cuda_runtime.h>

#define HH 128
#define WW 160
#define CCH 32
#define DD 48
#define NV 3
#define TH 16
#define TW 16
#define DC 10
#define NZ 5
#define HALO 18
#define HALO_PIX (HALO*HALO)
#define HWSZ (HH*WW)

// Scratch (static device allocations — allowed)
__device__ float4 g_featT4[NV*8*HWSZ];   // NCHW4: [v][c4 group (8)][y][x] -> float4 of 4 channels
__device__ float  g_cost[DD*HWSZ];       // cost volume [d][y][x]
__device__ float  g_rt[NV*12];           // per-view rot(9)+trans(3) of src_proj @ inv(ref_proj)

// ---------------------------------------------------------------------------
// Fused: repack features (V,C,H,W) -> NCHW4 AND compute warp matrices.
// ---------------------------------------------------------------------------
__global__ void __launch_bounds__(256) prep_kernel(const float* __restrict__ feat,
                                                   const float* __restrict__ proj) {
    if (blockIdx.x == 0 && threadIdx.x == 0) {
        float a[4][8];
        for (int r = 0; r < 4; r++)
            for (int c = 0; c < 4; c++) {
                a[r][c] = proj[r*4 + c];
                a[r][c+4] = (r == c) ? 1.f : 0.f;
            }
        for (int col = 0; col < 4; col++) {
            int piv = col;
            for (int r = col+1; r < 4; r++)
                if (fabsf(a[r][col]) > fabsf(a[piv][col])) piv = r;
            if (piv != col)
                for (int c = 0; c < 8; c++) { float t = a[col][c]; a[col][c] = a[piv][c]; a[piv][c] = t; }
            float d = 1.f / a[col][col];
            for (int c = 0; c < 8; c++) a[col][c] *= d;
            for (int r = 0; r < 4; r++) if (r != col) {
                float f = a[r][col];
                for (int c = 0; c < 8; c++) a[r][c] -= f * a[col][c];
            }
        }
        for (int v = 1; v < NV; v++) {
            const float* P = proj + v*16;
            for (int r = 0; r < 3; r++) {
                float m[4];
                for (int c = 0; c < 4; c++) {
                    float s = 0.f;
                    for (int k = 0; k < 4; k++) s += P[r*4 + k] * a[k][4 + c];
                    m[c] = s;
                }
                g_rt[v*12 + r*3 + 0] = m[0];
                g_rt[v*12 + r*3 + 1] = m[1];
                g_rt[v*12 + r*3 + 2] = m[2];
                g_rt[v*12 + 9 + r]   = m[3];
            }
        }
    }
    int gid = blockIdx.x * 256 + threadIdx.x;
    if (gid >= NV*8*HWSZ) return;
    int pix = gid % HWSZ;
    int rest = gid / HWSZ;
    int cc = rest & 7;
    int v  = rest >> 3;
    const float* src = feat + (size_t)(v*CCH + cc*4)*HWSZ + pix;
    float4 o;
    o.x = src[0];
    o.y = src[HWSZ];
    o.z = src[2*HWSZ];
    o.w = src[3*HWSZ];
    g_featT4[gid] = o;
}

// ---------------------------------------------------------------------------
// Packed f32x2 FMA helpers
// ---------------------------------------------------------------------------
__device__ __forceinline__ void fma2(unsigned long long &d, unsigned long long a, unsigned long long b) {
    asm("fma.rn.f32x2 %0, %1, %2, %0;" : "+l"(d) : "l"(a), "l"(b));
}
union F4U { float4 f; unsigned long long u[2]; };
union U2F { unsigned long long u; float2 f; };
__device__ __forceinline__ float pair_sum(unsigned long long a, unsigned long long b) {
    U2F pa, pb; pa.u = a; pb.u = b;
    return pa.f.x + pa.f.y + pb.f.x + pb.f.y;
}
__device__ __forceinline__ float4 shfl_down4(float4 v) {
    float4 r;
    r.x = __shfl_down_sync(0xffffffffu, v.x, 1);
    r.y = __shfl_down_sync(0xffffffffu, v.y, 1);
    r.z = __shfl_down_sync(0xffffffffu, v.z, 1);
    r.w = __shfl_down_sync(0xffffffffu, v.w, 1);
    return r;
}

// ---------------------------------------------------------------------------
// Fused: warp + variance (to SMEM) + 3x3x3 conv -> cost volume chunk
// grid (10, 8, 5) = 400 blocks, 128 threads, max 3 blocks/SM (balanced wave).
// Gather: separable row-sweep. Per (cc,view) each source row is loaded ONCE
// (lanes 0..18), horizontally blended via shfl, vertically blended against
// the previous row held in registers. ~2.2x fewer L1tex wavefronts than the
// per-pixel 4-tap scheme (the measured binding resource).
// ---------------------------------------------------------------------------
#define SMEM_VAR_BYTES  (8*HALO_PIX*16)       // 41472
#define SMEM_W_BYTES    (8*27*16)             // 3456
#define SMEM_COST_BYTES (DC*256*4)            // 10240
#define SMEM_RT_BYTES   (128)
#define SMEM_TOTAL (SMEM_VAR_BYTES + SMEM_W_BYTES + SMEM_COST_BYTES + SMEM_RT_BYTES)

__global__ void __launch_bounds__(128, 4) cost_kernel(const float* __restrict__ dvals,
                                                      const float* __restrict__ wt) {
    extern __shared__ char smem_raw[];
    float4* varsm  = (float4*)smem_raw;                                   // [cc][hh 18][ww 18]
    float4* wsm    = (float4*)(smem_raw + SMEM_VAR_BYTES);                // [cc][kw][kh][kd]
    float*  costsm = (float*)(smem_raw + SMEM_VAR_BYTES + SMEM_W_BYTES);  // [dl][pix 256]
    float*  rtsm   = (float*)(smem_raw + SMEM_VAR_BYTES + SMEM_W_BYTES + SMEM_COST_BYTES);

    const int tid  = threadIdx.x;
    const int lane = tid & 31;
    const int warp = tid >> 5;
    const int x0t = blockIdx.x * TW;
    const int y0t = blockIdx.y * TH;
    const int d0  = blockIdx.z * DC;

    // weights -> smem, layout [cc][kw][kh][kd] (float4 over 4 channels)
    for (int i = tid; i < 216; i += 128) {
        int cc = i / 27;
        int r  = i % 27;
        int kd = r / 9, kh = (r / 3) % 3, kw = r % 3;
        float4 wv;
        wv.x = wt[cc*108 +  0 + kd*9 + kh*3 + kw];
        wv.y = wt[cc*108 + 27 + kd*9 + kh*3 + kw];
        wv.z = wt[cc*108 + 54 + kd*9 + kh*3 + kw];
        wv.w = wt[cc*108 + 81 + kd*9 + kh*3 + kw];
        wsm[(cc*3 + kw)*9 + kh*3 + kd] = wv;
    }
    for (int i = tid; i < DC*256; i += 128) costsm[i] = 0.f;
    if (tid < 24) rtsm[tid] = g_rt[12 + tid];

    __syncthreads();

    const float4* __restrict__ FT = g_featT4;
    const float inv3 = 1.0f / 3.0f;

    for (int p = d0 - 1; p <= d0 + DC; ++p) {
        bool active = (p >= 0) & (p < DD);
        if (active) {
            const float dep = dvals[p];
            // Per-plane per-view uniform shift (projective map at tile center).
            int   isx[2], isy[2];
            float w0x[2], w1x[2], w0y[2], w1y[2];
#pragma unroll
            for (int v = 0; v < 2; v++) {
                const float* rt = rtsm + v*12;
                const float xc = (float)x0t + 7.5f, yc = (float)y0t + 7.5f;
                float pxv = (rt[0]*xc + rt[1]*yc + rt[2]) * dep + rt[9];
                float pyv = (rt[3]*xc + rt[4]*yc + rt[5]) * dep + rt[10];
                float pzv = (rt[6]*xc + rt[7]*yc + rt[8]) * dep + rt[11];
                float shx = __fdividef(pxv, pzv) - xc;
                float shy = __fdividef(pyv, pzv) - yc;
                float sxf = floorf(shx), syf = floorf(shy);
                isx[v] = (int)sxf;
                isy[v] = (int)syf;
                float fx1 = shx - sxf, fy1 = shy - syf;
                w0x[v] = 1.f - fx1; w1x[v] = fx1;
                w0y[v] = 1.f - fy1; w1y[v] = fy1;
            }
            // -------- phase 1: separable row-sweep gather, warp owns 2 ccs --
            for (int cc = warp; cc < 8; cc += 4) {
                const int cbase = cc*HWSZ;
                float4 hprev[2];
                for (int k = 0; k <= 18; k++) {
                    float4 hcur[2];
#pragma unroll
                    for (int v = 0; v < 2; v++) {
                        int ry = y0t - 1 + isy[v] + k;
                        int cx = x0t - 1 + isx[v] + lane;
                        float m = (((unsigned)ry < HH) && ((unsigned)cx < WW)) ? 1.f : 0.f;
                        int jy = min(max(ry, 0), HH-1);
                        int jx = min(max(cx, 0), WW-1);
                        float4 val = make_float4(0.f, 0.f, 0.f, 0.f);
                        if (lane < 19) {
                            val = FT[(v + 1)*8*HWSZ + cbase + jy*WW + jx];
                            val.x *= m; val.y *= m; val.z *= m; val.w *= m;
                        }
                        float4 nb = shfl_down4(val);
                        hcur[v].x = w0x[v]*val.x + w1x[v]*nb.x;
                        hcur[v].y = w0x[v]*val.y + w1x[v]*nb.y;
                        hcur[v].z = w0x[v]*val.z + w1x[v]*nb.z;
                        hcur[v].w = w0x[v]*val.w + w1x[v]*nb.w;
                    }
                    if (k >= 1 && lane < 18) {
                        const int hh = k - 1;
                        const int y = y0t + hh - 1;
                        const int x = x0t + lane - 1;
                        float4 var = make_float4(0.f, 0.f, 0.f, 0.f);
                        if ((unsigned)y < HH && (unsigned)x < WW) {
                            float4 rf = FT[cbase + y*WW + x];
                            float4 o1, o2;
                            o1.x = w0y[0]*hprev[0].x + w1y[0]*hcur[0].x;
                            o1.y = w0y[0]*hprev[0].y + w1y[0]*hcur[0].y;
                            o1.z = w0y[0]*hprev[0].z + w1y[0]*hcur[0].z;
                            o1.w = w0y[0]*hprev[0].w + w1y[0]*hcur[0].w;
                            o2.x = w0y[1]*hprev[1].x + w1y[1]*hcur[1].x;
                            o2.y = w0y[1]*hprev[1].y + w1y[1]*hcur[1].y;
                            o2.z = w0y[1]*hprev[1].z + w1y[1]*hcur[1].z;
                            o2.w = w0y[1]*hprev[1].w + w1y[1]*hcur[1].w;
                            float sx = rf.x + o1.x + o2.x;
                            float sy = rf.y + o1.y + o2.y;
                            float sz = rf.z + o1.z + o2.z;
                            float sw = rf.w + o1.w + o2.w;
                            float qx = rf.x*rf.x + o1.x*o1.x + o2.x*o2.x;
                            float qy = rf.y*rf.y + o1.y*o1.y + o2.y*o2.y;
                            float qz = rf.z*rf.z + o1.z*o1.z + o2.z*o2.z;
                            float qw = rf.w*rf.w + o1.w*o1.w + o2.w*o2.w;
                            float mx = sx*inv3, my = sy*inv3, mz = sz*inv3, mw = sw*inv3;
                            var.x = qx*inv3 - mx*mx;
                            var.y = qy*inv3 - my*my;
                            var.z = qz*inv3 - mz*mz;
                            var.w = qw*inv3 - mw*mw;
                        }
                        varsm[(cc*HALO + hh)*HALO + lane] = var;
                    }
                    hprev[0] = hcur[0];
                    hprev[1] = hcur[1];
                }
                // fill ww = 18 column (pixels at x = x0t+17) — wait, HALO=18 cols
                // cover ww 0..17 only; lane 18 writes nothing. Column count is 18,
                // rows 18: fully covered by lanes 0..17. (no-op)
            }
        }
        __syncthreads();
        if (active) {
            // -------- phase 2: conv reduction, 2 output rows / thread ----
            const int wl = tid & 15;
            const int r0 = (tid >> 4) << 1;
            unsigned long long accA[2][3], accB[2][3];
#pragma unroll
            for (int px = 0; px < 2; px++)
#pragma unroll
                for (int kd = 0; kd < 3; kd++) { accA[px][kd] = 0ULL; accB[px][kd] = 0ULL; }

            for (int cc = 0; cc < 8; cc++) {
#pragma unroll
                for (int kw = 0; kw < 3; kw++) {
                    F4U wv[9];
                    const float4* wp = wsm + (cc*3 + kw)*9;
#pragma unroll
                    for (int k = 0; k < 9; k++) wv[k].f = wp[k];
                    F4U v0, v1, v2, v3;
                    v0.f = varsm[(cc*HALO + r0 + 0)*HALO + wl + kw];
                    v1.f = varsm[(cc*HALO + r0 + 1)*HALO + wl + kw];
                    v2.f = varsm[(cc*HALO + r0 + 2)*HALO + wl + kw];
                    v3.f = varsm[(cc*HALO + r0 + 3)*HALO + wl + kw];
#pragma unroll
                    for (int kd = 0; kd < 3; kd++) {
                        fma2(accA[0][kd], v0.u[0], wv[0+kd].u[0]); fma2(accB[0][kd], v0.u[1], wv[0+kd].u[1]);
                        fma2(accA[0][kd], v1.u[0], wv[3+kd].u[0]); fma2(accB[0][kd], v1.u[1], wv[3+kd].u[1]);
                        fma2(accA[0][kd], v2.u[0], wv[6+kd].u[0]); fma2(accB[0][kd], v2.u[1], wv[6+kd].u[1]);
                        fma2(accA[1][kd], v1.u[0], wv[0+kd].u[0]); fma2(accB[1][kd], v1.u[1], wv[0+kd].u[1]);
                        fma2(accA[1][kd], v2.u[0], wv[3+kd].u[0]); fma2(accB[1][kd], v2.u[1], wv[3+kd].u[1]);
                        fma2(accA[1][kd], v3.u[0], wv[6+kd].u[0]); fma2(accB[1][kd], v3.u[1], wv[6+kd].u[1]);
                    }
                }
            }
            int pix0 = r0*16 + wl;
#pragma unroll
            for (int kd = 0; kd < 3; kd++) {
                int dl = p + 1 - kd - d0;
                if (dl >= 0 && dl < DC) {
                    costsm[dl*256 + pix0]      += pair_sum(accA[0][kd], accB[0][kd]);
                    costsm[dl*256 + pix0 + 16] += pair_sum(accA[1][kd], accB[1][kd]);
                }
            }
        }
        __syncthreads();
    }

    // write cost chunk (clamp: last z-chunk extends past DD)
    for (int i = tid; i < DC*256; i += 128) {
        int dl = i >> 8;
        if (d0 + dl >= DD) break;
        int pix = i & 255;
        int r = pix >> 4, wl2 = pix & 15;
        g_cost[(size_t)(d0 + dl)*HWSZ + (y0t + r)*WW + x0t + wl2] = costsm[i];
    }
}

// ---------------------------------------------------------------------------
// Softmax over depth + regression + confidence
// ---------------------------------------------------------------------------
__global__ void __launch_bounds__(256) finalize(const float* __restrict__ dvals,
                                                float* __restrict__ out) {
    int pix = blockIdx.x * 256 + threadIdx.x;
    if (pix >= HWSZ) return;
    float cv[DD];
#pragma unroll
    for (int d = 0; d < DD; d++) cv[d] = g_cost[(size_t)d*HWSZ + pix];
    float m = cv[0];
#pragma unroll
    for (int d = 1; d < DD; d++) m = fmaxf(m, cv[d]);
    float sum = 0.f;
#pragma unroll
    for (int d = 0; d < DD; d++) { cv[d] = __expf(cv[d] - m); sum += cv[d]; }
    float inv = 1.0f / sum;
    float dep = 0.f, di = 0.f;
#pragma unroll
    for (int d = 0; d < DD; d++) {
        float pr = cv[d] * inv;
        dep += pr * dvals[d];
        di  += pr * (float)d;
    }
    int didx = (int)di;
    didx = min(max(didx, 0), DD - 1);
    float conf = 0.f;
#pragma unroll
    for (int d = 0; d < DD; d++)
        if (d >= didx - 1 && d <= didx + 2) conf += cv[d];
    conf *= inv;
    out[pix] = dep;
    out[HWSZ + pix] = conf;
}

// ---------------------------------------------------------------------------
extern "C" void kernel_launch(void* const* d_in, const int* in_sizes, int n_in,
                              void* d_out, int out_size) {
    const float* features = (const float*)d_in[0];
    const float* proj     = (const float*)d_in[1];
    const float* dvals    = (const float*)d_in[2];
    const float* wt       = (const float*)d_in[3];
    // d_in[4] = reg_bias: constant over depth -> softmax-invariant, unused.
    float* out = (float*)d_out;

    prep_kernel<<<(NV*8*HWSZ + 255)/256, 256>>>(features, proj);
    cudaFuncSetAttribute(cost_kernel, cudaFuncAttributeMaxDynamicSharedMemorySize, SMEM_TOTAL);
    cost_kernel<<<dim3(WW/TW, HH/TH, NZ), 128, SMEM_TOTAL>>>(dvals, wt);
    finalize<<<HWSZ/256, 256>>>(dvals, out);
}

// round 14
// speedup vs baseline: 2.3208x; 2.3208x over previous
#include <cuda_runtime.h>

#define HH 128
#define WW 160
#define CCH 32
#define DD 48
#define NV 3
#define TH 16
#define TW 16
#define DC 10
#define NZ 5
#define HALO 18
#define HALO_PIX (HALO*HALO)
#define HWSZ (HH*WW)

// Scratch (static device allocations — allowed)
__device__ float4 g_featT4[NV*8*HWSZ];   // NCHW4: [v][c4 group (8)][y][x] -> float4 of 4 channels
__device__ float  g_cost[DD*HWSZ];       // cost volume [d][y][x]
__device__ float  g_rt[NV*12];           // per-view rot(9)+trans(3) of src_proj @ inv(ref_proj)

// ---------------------------------------------------------------------------
// Fused: repack features (V,C,H,W) -> NCHW4 AND compute warp matrices.
// ---------------------------------------------------------------------------
__global__ void __launch_bounds__(256) prep_kernel(const float* __restrict__ feat,
                                                   const float* __restrict__ proj) {
    if (blockIdx.x == 0 && threadIdx.x == 0) {
        float a[4][8];
        for (int r = 0; r < 4; r++)
            for (int c = 0; c < 4; c++) {
                a[r][c] = proj[r*4 + c];
                a[r][c+4] = (r == c) ? 1.f : 0.f;
            }
        for (int col = 0; col < 4; col++) {
            int piv = col;
            for (int r = col+1; r < 4; r++)
                if (fabsf(a[r][col]) > fabsf(a[piv][col])) piv = r;
            if (piv != col)
                for (int c = 0; c < 8; c++) { float t = a[col][c]; a[col][c] = a[piv][c]; a[piv][c] = t; }
            float d = 1.f / a[col][col];
            for (int c = 0; c < 8; c++) a[col][c] *= d;
            for (int r = 0; r < 4; r++) if (r != col) {
                float f = a[r][col];
                for (int c = 0; c < 8; c++) a[r][c] -= f * a[col][c];
            }
        }
        for (int v = 1; v < NV; v++) {
            const float* P = proj + v*16;
            for (int r = 0; r < 3; r++) {
                float m[4];
                for (int c = 0; c < 4; c++) {
                    float s = 0.f;
                    for (int k = 0; k < 4; k++) s += P[r*4 + k] * a[k][4 + c];
                    m[c] = s;
                }
                g_rt[v*12 + r*3 + 0] = m[0];
                g_rt[v*12 + r*3 + 1] = m[1];
                g_rt[v*12 + r*3 + 2] = m[2];
                g_rt[v*12 + 9 + r]   = m[3];
            }
        }
    }
    int gid = blockIdx.x * 256 + threadIdx.x;
    if (gid >= NV*8*HWSZ) return;
    int pix = gid % HWSZ;
    int rest = gid / HWSZ;
    int cc = rest & 7;
    int v  = rest >> 3;
    const float* src = feat + (size_t)(v*CCH + cc*4)*HWSZ + pix;
    float4 o;
    o.x = src[0];
    o.y = src[HWSZ];
    o.z = src[2*HWSZ];
    o.w = src[3*HWSZ];
    g_featT4[gid] = o;
}

// ---------------------------------------------------------------------------
// Packed f32x2 FMA helpers
// ---------------------------------------------------------------------------
__device__ __forceinline__ void fma2(unsigned long long &d, unsigned long long a, unsigned long long b) {
    asm("fma.rn.f32x2 %0, %1, %2, %0;" : "+l"(d) : "l"(a), "l"(b));
}
union F4U { float4 f; unsigned long long u[2]; };
union U2F { unsigned long long u; float2 f; };
__device__ __forceinline__ float pair_sum(unsigned long long a, unsigned long long b) {
    U2F pa, pb; pa.u = a; pb.u = b;
    return pa.f.x + pa.f.y + pb.f.x + pb.f.y;
}

// ---------------------------------------------------------------------------
// Fused: warp + variance (to SMEM) + 3x3x3 conv -> cost volume chunk
// grid (10, 8, 5) = 400 blocks, 128 threads, max 3 blocks/SM (balanced wave).
// Gather: each thread owns 3 VERTICALLY adjacent halo pixels; the bilinear
// taps of adjacent pixels share interior rows, so per view only 4 tap rows x
// 2 cols = 8 independent loads serve 3 pixels (19 LDG/task/cc vs 27).
// Loads stay per-thread independent (full MLP), lanes coalesced as in R12.
// ---------------------------------------------------------------------------
#define SMEM_VAR_BYTES  (8*HALO_PIX*16)       // 41472
#define SMEM_W_BYTES    (8*27*16)             // 3456
#define SMEM_COST_BYTES (DC*256*4)            // 10240
#define SMEM_RT_BYTES   (128)
#define SMEM_TOTAL (SMEM_VAR_BYTES + SMEM_W_BYTES + SMEM_COST_BYTES + SMEM_RT_BYTES)

__global__ void __launch_bounds__(128, 4) cost_kernel(const float* __restrict__ dvals,
                                                      const float* __restrict__ wt) {
    extern __shared__ char smem_raw[];
    float4* varsm  = (float4*)smem_raw;                                   // [cc][hh 18][ww 18]
    float4* wsm    = (float4*)(smem_raw + SMEM_VAR_BYTES);                // [cc][kw][kh][kd]
    float*  costsm = (float*)(smem_raw + SMEM_VAR_BYTES + SMEM_W_BYTES);  // [dl][pix 256]
    float*  rtsm   = (float*)(smem_raw + SMEM_VAR_BYTES + SMEM_W_BYTES + SMEM_COST_BYTES);

    const int tid = threadIdx.x;
    const int x0t = blockIdx.x * TW;
    const int y0t = blockIdx.y * TH;
    const int d0  = blockIdx.z * DC;

    // weights -> smem, layout [cc][kw][kh][kd] (float4 over 4 channels)
    for (int i = tid; i < 216; i += 128) {
        int cc = i / 27;
        int r  = i % 27;
        int kd = r / 9, kh = (r / 3) % 3, kw = r % 3;
        float4 wv;
        wv.x = wt[cc*108 +  0 + kd*9 + kh*3 + kw];
        wv.y = wt[cc*108 + 27 + kd*9 + kh*3 + kw];
        wv.z = wt[cc*108 + 54 + kd*9 + kh*3 + kw];
        wv.w = wt[cc*108 + 81 + kd*9 + kh*3 + kw];
        wsm[(cc*3 + kw)*9 + kh*3 + kd] = wv;
    }
    for (int i = tid; i < DC*256; i += 128) costsm[i] = 0.f;
    if (tid < 24) rtsm[tid] = g_rt[12 + tid];

    __syncthreads();

    const float4* __restrict__ FT = g_featT4;
    const float inv3 = 1.0f / 3.0f;

    // task layout: tid < 108, row-triple = tid/18, col = tid%18
    const int ww  = tid % 18;
    const int hh0 = (tid / 18) * 3;
    const int x   = x0t + ww - 1;          // ref x for this task
    const int y0p = y0t + hh0 - 1;         // ref y of first pixel
    const float mcolref = ((unsigned)x < WW) ? 1.f : 0.f;
    const int jxr = min(max(x, 0), WW-1);

    for (int p = d0 - 1; p <= d0 + DC; ++p) {
        bool active = (p >= 0) & (p < DD);
        if (active) {
            const float dep = dvals[p];
            // Per-plane per-view uniform shift (projective map at tile center).
            int   isx[2], isy[2];
            float w0x[2], w1x[2], w0y[2], w1y[2];
#pragma unroll
            for (int v = 0; v < 2; v++) {
                const float* rt = rtsm + v*12;
                const float xc = (float)x0t + 7.5f, yc = (float)y0t + 7.5f;
                float pxv = (rt[0]*xc + rt[1]*yc + rt[2]) * dep + rt[9];
                float pyv = (rt[3]*xc + rt[4]*yc + rt[5]) * dep + rt[10];
                float pzv = (rt[6]*xc + rt[7]*yc + rt[8]) * dep + rt[11];
                float shx = __fdividef(pxv, pzv) - xc;
                float shy = __fdividef(pyv, pzv) - yc;
                float sxf = floorf(shx), syf = floorf(shy);
                isx[v] = (int)sxf;
                isy[v] = (int)syf;
                float fx1 = shx - sxf, fy1 = shy - syf;
                w0x[v] = 1.f - fx1; w1x[v] = fx1;
                w0y[v] = 1.f - fy1; w1y[v] = fy1;
            }
            if (tid < 108) {
                // per-view geometry for this task (plane-dependent, cc-invariant)
                int   jy[2][4], jx0[2], jx1[2];
                float mr[2][4], mc0[2], mc1[2];
#pragma unroll
                for (int v = 0; v < 2; v++) {
                    int cx0 = x + isx[v];
                    mc0[v] = ((unsigned)cx0     < WW) ? 1.f : 0.f;
                    mc1[v] = ((unsigned)(cx0+1) < WW) ? 1.f : 0.f;
                    jx0[v] = min(max(cx0,     0), WW-1);
                    jx1[v] = min(max(cx0 + 1, 0), WW-1);
#pragma unroll
                    for (int r = 0; r < 4; r++) {
                        int ry = y0p + isy[v] + r;
                        mr[v][r] = ((unsigned)ry < HH) ? 1.f : 0.f;
                        jy[v][r] = min(max(ry, 0), HH-1);
                    }
                }
                // per-pixel ref validity + clamped ref rows
                float pv[3];
                int   jyr[3];
#pragma unroll
                for (int j = 0; j < 3; j++) {
                    int yj = y0p + j;
                    pv[j]  = (((unsigned)yj < HH) ? 1.f : 0.f) * mcolref;
                    jyr[j] = min(max(yj, 0), HH-1);
                }

                for (int cc = 0; cc < 8; cc++) {
                    const int cbase = cc*HWSZ;
                    // ref pixels
                    float4 s[3], q[3];
#pragma unroll
                    for (int j = 0; j < 3; j++) {
                        float4 rf = FT[cbase + jyr[j]*WW + jxr];
                        s[j] = rf;
                        q[j].x = rf.x*rf.x; q[j].y = rf.y*rf.y;
                        q[j].z = rf.z*rf.z; q[j].w = rf.w*rf.w;
                    }
#pragma unroll
                    for (int v = 0; v < 2; v++) {
                        const int base = (v + 1)*8*HWSZ + cbase;
                        // 4 shared tap rows x 2 cols, 8 independent loads
                        float4 h[4];
#pragma unroll
                        for (int r = 0; r < 4; r++) {
                            float4 ta = FT[base + jy[v][r]*WW + jx0[v]];
                            float4 tb = FT[base + jy[v][r]*WW + jx1[v]];
                            float wa = w0x[v]*mr[v][r]*mc0[v];
                            float wb = w1x[v]*mr[v][r]*mc1[v];
                            h[r].x = wa*ta.x + wb*tb.x;
                            h[r].y = wa*ta.y + wb*tb.y;
                            h[r].z = wa*ta.z + wb*tb.z;
                            h[r].w = wa*ta.w + wb*tb.w;
                        }
#pragma unroll
                        for (int j = 0; j < 3; j++) {
                            float4 o;
                            o.x = w0y[v]*h[j].x + w1y[v]*h[j+1].x;
                            o.y = w0y[v]*h[j].y + w1y[v]*h[j+1].y;
                            o.z = w0y[v]*h[j].z + w1y[v]*h[j+1].z;
                            o.w = w0y[v]*h[j].w + w1y[v]*h[j+1].w;
                            s[j].x += o.x; q[j].x += o.x*o.x;
                            s[j].y += o.y; q[j].y += o.y*o.y;
                            s[j].z += o.z; q[j].z += o.z*o.z;
                            s[j].w += o.w; q[j].w += o.w*o.w;
                        }
                    }
#pragma unroll
                    for (int j = 0; j < 3; j++) {
                        float mx = s[j].x*inv3, my = s[j].y*inv3;
                        float mz = s[j].z*inv3, mw = s[j].w*inv3;
                        float4 var;
                        var.x = (q[j].x*inv3 - mx*mx) * pv[j];
                        var.y = (q[j].y*inv3 - my*my) * pv[j];
                        var.z = (q[j].z*inv3 - mz*mz) * pv[j];
                        var.w = (q[j].w*inv3 - mw*mw) * pv[j];
                        varsm[(cc*HALO + hh0 + j)*HALO + ww] = var;
                    }
                }
            }
        }
        __syncthreads();
        if (active) {
            // -------- phase 2: conv reduction, 2 output rows / thread ----
            const int wl = tid & 15;
            const int r0 = (tid >> 4) << 1;
            unsigned long long accA[2][3], accB[2][3];
#pragma unroll
            for (int px = 0; px < 2; px++)
#pragma unroll
                for (int kd = 0; kd < 3; kd++) { accA[px][kd] = 0ULL; accB[px][kd] = 0ULL; }

            for (int cc = 0; cc < 8; cc++) {
#pragma unroll
                for (int kw = 0; kw < 3; kw++) {
                    F4U wv[9];
                    const float4* wp = wsm + (cc*3 + kw)*9;
#pragma unroll
                    for (int k = 0; k < 9; k++) wv[k].f = wp[k];
                    F4U v0, v1, v2, v3;
                    v0.f = varsm[(cc*HALO + r0 + 0)*HALO + wl + kw];
                    v1.f = varsm[(cc*HALO + r0 + 1)*HALO + wl + kw];
                    v2.f = varsm[(cc*HALO + r0 + 2)*HALO + wl + kw];
                    v3.f = varsm[(cc*HALO + r0 + 3)*HALO + wl + kw];
#pragma unroll
                    for (int kd = 0; kd < 3; kd++) {
                        fma2(accA[0][kd], v0.u[0], wv[0+kd].u[0]); fma2(accB[0][kd], v0.u[1], wv[0+kd].u[1]);
                        fma2(accA[0][kd], v1.u[0], wv[3+kd].u[0]); fma2(accB[0][kd], v1.u[1], wv[3+kd].u[1]);
                        fma2(accA[0][kd], v2.u[0], wv[6+kd].u[0]); fma2(accB[0][kd], v2.u[1], wv[6+kd].u[1]);
                        fma2(accA[1][kd], v1.u[0], wv[0+kd].u[0]); fma2(accB[1][kd], v1.u[1], wv[0+kd].u[1]);
                        fma2(accA[1][kd], v2.u[0], wv[3+kd].u[0]); fma2(accB[1][kd], v2.u[1], wv[3+kd].u[1]);
                        fma2(accA[1][kd], v3.u[0], wv[6+kd].u[0]); fma2(accB[1][kd], v3.u[1], wv[6+kd].u[1]);
                    }
                }
            }
            int pix0 = r0*16 + wl;
#pragma unroll
            for (int kd = 0; kd < 3; kd++) {
                int dl = p + 1 - kd - d0;
                if (dl >= 0 && dl < DC) {
                    costsm[dl*256 + pix0]      += pair_sum(accA[0][kd], accB[0][kd]);
                    costsm[dl*256 + pix0 + 16] += pair_sum(accA[1][kd], accB[1][kd]);
                }
            }
        }
        __syncthreads();
    }

    // write cost chunk (clamp: last z-chunk extends past DD)
    for (int i = tid; i < DC*256; i += 128) {
        int dl = i >> 8;
        if (d0 + dl >= DD) break;
        int pix = i & 255;
        int r = pix >> 4, wl2 = pix & 15;
        g_cost[(size_t)(d0 + dl)*HWSZ + (y0t + r)*WW + x0t + wl2] = costsm[i];
    }
}

// ---------------------------------------------------------------------------
// Softmax over depth + regression + confidence
// ---------------------------------------------------------------------------
__global__ void __launch_bounds__(256) finalize(const float* __restrict__ dvals,
                                                float* __restrict__ out) {
    int pix = blockIdx.x * 256 + threadIdx.x;
    if (pix >= HWSZ) return;
    float cv[DD];
#pragma unroll
    for (int d = 0; d < DD; d++) cv[d] = g_cost[(size_t)d*HWSZ + pix];
    float m = cv[0];
#pragma unroll
    for (int d = 1; d < DD; d++) m = fmaxf(m, cv[d]);
    float sum = 0.f;
#pragma unroll
    for (int d = 0; d < DD; d++) { cv[d] = __expf(cv[d] - m); sum += cv[d]; }
    float inv = 1.0f / sum;
    float dep = 0.f, di = 0.f;
#pragma unroll
    for (int d = 0; d < DD; d++) {
        float pr = cv[d] * inv;
        dep += pr * dvals[d];
        di  += pr * (float)d;
    }
    int didx = (int)di;
    didx = min(max(didx, 0), DD - 1);
    float conf = 0.f;
#pragma unroll
    for (int d = 0; d < DD; d++)
        if (d >= didx - 1 && d <= didx + 2) conf += cv[d];
    conf *= inv;
    out[pix] = dep;
    out[HWSZ + pix] = conf;
}

// ---------------------------------------------------------------------------
extern "C" void kernel_launch(void* const* d_in, const int* in_sizes, int n_in,
                              void* d_out, int out_size) {
    const float* features = (const float*)d_in[0];
    const float* proj     = (const float*)d_in[1];
    const float* dvals    = (const float*)d_in[2];
    const float* wt       = (const float*)d_in[3];
    // d_in[4] = reg_bias: constant over depth -> softmax-invariant, unused.
    float* out = (float*)d_out;

    prep_kernel<<<(NV*8*HWSZ + 255)/256, 256>>>(features, proj);
    cudaFuncSetAttribute(cost_kernel, cudaFuncAttributeMaxDynamicSharedMemorySize, SMEM_TOTAL);
    cost_kernel<<<dim3(WW/TW, HH/TH, NZ), 128, SMEM_TOTAL>>>(dvals, wt);
    finalize<<<HWSZ/256, 256>>>(dvals, out);
}